// round 1
// baseline (speedup 1.0000x reference)
#include <cuda_runtime.h>

#define SDIM 2048
#define EDIM 256
#define BDIM 8

// Scratch (allocation-free rule: __device__ globals)
__device__ float g_Wqt[EDIM * EDIM];           // Wq transposed: Wqt[e][f] = Wq[f][e]
__device__ float g_Wot[EDIM * EDIM];           // Wo transposed
__device__ float g_Q[BDIM * SDIM * EDIM];      // Qt[b][s][f]
__device__ float g_attn[BDIM * SDIM * 16];     // 9 weights per (b,s), stride 16
__device__ float g_pool[BDIM * SDIM * EDIM];   // pooled[b][e][s]

// ---------------------------------------------------------------------------
// Weight transpose: Wt[e][f] = W[f][e]
// ---------------------------------------------------------------------------
__global__ void transpose_k(const float* __restrict__ Wq, const float* __restrict__ Wo) {
    __shared__ float tile[32][33];
    const float* src = blockIdx.z ? Wo : Wq;
    float* dst = blockIdx.z ? g_Wot : g_Wqt;
    int x0 = blockIdx.x * 32, y0 = blockIdx.y * 32;
    int tx = threadIdx.x, ty = threadIdx.y;  // 32 x 8
#pragma unroll
    for (int i = 0; i < 32; i += 8)
        tile[ty + i][tx] = src[(y0 + ty + i) * EDIM + x0 + tx];
    __syncthreads();
#pragma unroll
    for (int i = 0; i < 32; i += 8)
        dst[(x0 + ty + i) * EDIM + y0 + tx] = tile[tx][ty + i];
}

// ---------------------------------------------------------------------------
// GEMM: C[m][n] = (sum_k A[k][m] * B[k][n] + bias) * scale
// A, B given K-major (row k, contiguous m / n). 128x128 tile, BK=8,
// 256 threads, 8x8 per-thread frags (split 4+4), double-buffered smem.
// BIAS_M: bias indexed by m (else by n).
// ---------------------------------------------------------------------------
template <int BIAS_M>
__global__ void __launch_bounds__(256, 2) gemm128(
    const float* __restrict__ A, int lda, long strideA,
    const float* __restrict__ Bm, int ldb, long strideB,
    float* __restrict__ C, int ldc, long strideC,
    const float* __restrict__ bias, float scale) {
    int bm = blockIdx.y * 128;
    int bn = blockIdx.x * 128;
    int z = blockIdx.z;
    A += (long)z * strideA;
    Bm += (long)z * strideB;
    C += (long)z * strideC;

    __shared__ float As[2][8][128];
    __shared__ float Bs[2][8][128];

    int tid = threadIdx.x;
    int lr = tid >> 5;          // 0..7  (k row for global loads)
    int lc = (tid & 31) << 2;   // 0..124

    const float* Ag = A + (long)lr * lda + bm + lc;
    const float* Bg = Bm + (long)lr * ldb + bn + lc;

    int tm = (tid >> 4) << 2;   // 0..60
    int tn = (tid & 15) << 2;   // 0..60

    float acc[8][8];
#pragma unroll
    for (int i = 0; i < 8; i++)
#pragma unroll
        for (int j = 0; j < 8; j++) acc[i][j] = 0.0f;

    // preload stage 0
    {
        float4 a = *(const float4*)Ag;
        float4 b = *(const float4*)Bg;
        *(float4*)&As[0][lr][lc] = a;
        *(float4*)&Bs[0][lr][lc] = b;
    }
    __syncthreads();

    const int KT = EDIM / 8;  // 32
    float4 anx, bnx;
    for (int kt = 0; kt < KT; kt++) {
        int cur = kt & 1, nxt = cur ^ 1;
        if (kt + 1 < KT) {
            anx = *(const float4*)(Ag + (long)(kt + 1) * 8 * lda);
            bnx = *(const float4*)(Bg + (long)(kt + 1) * 8 * ldb);
        }
#pragma unroll
        for (int k = 0; k < 8; k++) {
            float ar[8], br[8];
            *(float4*)&ar[0] = *(float4*)&As[cur][k][tm];
            *(float4*)&ar[4] = *(float4*)&As[cur][k][tm + 64];
            *(float4*)&br[0] = *(float4*)&Bs[cur][k][tn];
            *(float4*)&br[4] = *(float4*)&Bs[cur][k][tn + 64];
#pragma unroll
            for (int i = 0; i < 8; i++)
#pragma unroll
                for (int j = 0; j < 8; j++) acc[i][j] += ar[i] * br[j];
        }
        if (kt + 1 < KT) {
            *(float4*)&As[nxt][lr][lc] = anx;
            *(float4*)&Bs[nxt][lr][lc] = bnx;
            __syncthreads();
        }
    }

    // epilogue
#pragma unroll
    for (int i = 0; i < 8; i++) {
        int m = bm + ((i < 4) ? (tm + i) : (64 + tm + i - 4));
#pragma unroll
        for (int jj = 0; jj < 2; jj++) {
            int n = bn + tn + jj * 64;
            float out[4];
#pragma unroll
            for (int j = 0; j < 4; j++) {
                float bv = BIAS_M ? bias[m] : bias[n + j];
                out[j] = (acc[i][jj * 4 + j] + bv) * scale;
            }
            *(float4*)&C[(long)m * ldc + n] = make_float4(out[0], out[1], out[2], out[3]);
        }
    }
}

// ---------------------------------------------------------------------------
// Attention weights: for each (b,s), d_l = Qcol(s) . Qcol(s+l-4) (OOB -> bq),
// softmax over l of d_l/24 -> g_attn. Block: 32 s positions, 40-col smem tile.
// ---------------------------------------------------------------------------
__global__ void __launch_bounds__(256) attn_kernel(const float* __restrict__ bq) {
    int b = blockIdx.y;
    int s0 = blockIdx.x * 32;
    __shared__ float Qs[40 * EDIM];  // cols s0-4 .. s0+35

    const float* Qb = g_Q + (long)b * SDIM * EDIM;
    for (int idx = threadIdx.x; idx < 40 * 64; idx += 256) {
        int c = idx >> 6, v = idx & 63;
        int s = s0 - 4 + c;
        float4 val;
        if (s < 0 || s >= SDIM)
            val = ((const float4*)bq)[v];
        else
            val = ((const float4*)(Qb + (long)s * EDIM))[v];
        ((float4*)Qs)[c * 64 + v] = val;
    }
    __syncthreads();

    int w = threadIdx.x >> 5, lane = threadIdx.x & 31;
    const float inv_scale = 1.0f / 24.0f;
#pragma unroll
    for (int i = 0; i < 4; i++) {
        int ls = w * 4 + i;
        int cc = ls + 4;
        float4 c0 = ((float4*)Qs)[cc * 64 + lane];
        float4 c1 = ((float4*)Qs)[cc * 64 + 32 + lane];
        float myd = -1e30f;
#pragma unroll
        for (int l = 0; l < 9; l++) {
            int cl = cc + l - 4;
            float4 q0 = ((float4*)Qs)[cl * 64 + lane];
            float4 q1 = ((float4*)Qs)[cl * 64 + 32 + lane];
            float p = c0.x * q0.x + c0.y * q0.y + c0.z * q0.z + c0.w * q0.w +
                      c1.x * q1.x + c1.y * q1.y + c1.z * q1.z + c1.w * q1.w;
#pragma unroll
            for (int off = 16; off; off >>= 1) p += __shfl_xor_sync(0xffffffffu, p, off);
            if (lane == l) myd = p;
        }
        float eng = myd * inv_scale;
        float m = eng;
#pragma unroll
        for (int off = 16; off; off >>= 1) m = fmaxf(m, __shfl_xor_sync(0xffffffffu, m, off));
        float ev = (lane < 9) ? __expf(eng - m) : 0.0f;
        float sum = ev;
#pragma unroll
        for (int off = 16; off; off >>= 1) sum += __shfl_xor_sync(0xffffffffu, sum, off);
        float a = ev / sum;
        if (lane < 9) g_attn[(long)(b * SDIM + s0 + ls) * 16 + lane] = a;
    }
}

// ---------------------------------------------------------------------------
// Weighted pooling: pooled[b][e][s] = sum_l a[b][s][l] * x[b][e][s+l-4]
// Block: 32 e-rows x 128 s. Threads 256 = 32(s) x 8(e), 4x4 outputs each.
// ---------------------------------------------------------------------------
__global__ void __launch_bounds__(256) pool_kernel(const float* __restrict__ x) {
    int b = blockIdx.z;
    int e0 = blockIdx.y * 32;
    int s0 = blockIdx.x * 128;
    __shared__ float a_sm[128 * 9];
    __shared__ float x_sm[32 * 136];

    for (int idx = threadIdx.x; idx < 128 * 9; idx += 256) {
        int i = idx / 9, l = idx - i * 9;
        a_sm[idx] = g_attn[(long)(b * SDIM + s0 + i) * 16 + l];
    }
    const float* xb = x + ((long)b * EDIM + e0) * SDIM;
    for (int idx = threadIdx.x; idx < 32 * 136; idx += 256) {
        int e = idx / 136, j = idx - e * 136;
        int s = s0 - 4 + j;
        x_sm[idx] = (s >= 0 && s < SDIM) ? xb[(long)e * SDIM + s] : 0.0f;
    }
    __syncthreads();

    int ts = threadIdx.x & 31, te = threadIdx.x >> 5;
    float* poolb = g_pool + ((long)b * EDIM + e0) * SDIM + s0;
#pragma unroll
    for (int si = 0; si < 4; si++) {
        int ls = ts + si * 32;
        float a[9];
#pragma unroll
        for (int l = 0; l < 9; l++) a[l] = a_sm[ls * 9 + l];
#pragma unroll
        for (int ei = 0; ei < 4; ei++) {
            int e = te + ei * 8;
            float acc = 0.0f;
#pragma unroll
            for (int l = 0; l < 9; l++) acc += a[l] * x_sm[e * 136 + ls + l];
            poolb[(long)e * SDIM + ls] = acc;
        }
    }
}

// ---------------------------------------------------------------------------
extern "C" void kernel_launch(void* const* d_in, const int* in_sizes, int n_in,
                              void* d_out, int out_size) {
    const float* x  = (const float*)d_in[0];
    const float* Wq = (const float*)d_in[1];
    const float* bq = (const float*)d_in[2];
    const float* Wo = (const float*)d_in[3];
    const float* bo = (const float*)d_in[4];
    float* out = (float*)d_out;

    float *Wqt, *Wot, *Qp, *poolp;
    cudaGetSymbolAddress((void**)&Wqt, g_Wqt);
    cudaGetSymbolAddress((void**)&Wot, g_Wot);
    cudaGetSymbolAddress((void**)&Qp, g_Q);
    cudaGetSymbolAddress((void**)&poolp, g_pool);

    // 1) transpose weights
    transpose_k<<<dim3(8, 8, 2), dim3(32, 8)>>>(Wq, Wo);

    // 2) Qt[b][s][f] = sum_e x[b][e][s]*Wqt[e][f] + bq[f]
    //    A = x[b] (k=e stride S, m=s), B = Wqt (k=e stride E, n=f)
    gemm128<0><<<dim3(2, 16, BDIM), 256>>>(
        x, SDIM, (long)EDIM * SDIM,
        Wqt, EDIM, 0,
        Qp, EDIM, (long)SDIM * EDIM,
        bq, 1.0f);

    // 3) attention weights
    attn_kernel<<<dim3(SDIM / 32, BDIM), 256>>>(bq);

    // 4) weighted pooling
    pool_kernel<<<dim3(SDIM / 128, EDIM / 32, BDIM), 256>>>(x);

    // 5) out[b][f][s] = (sum_e pooled[b][e][s]*Wo[f][e] + bo[f]) / 9
    //    A = Wot (k=e stride E, m=f), B = pooled[b] (k=e stride S, n=s)
    gemm128<1><<<dim3(16, 2, BDIM), 256>>>(
        Wot, EDIM, 0,
        poolp, SDIM, (long)EDIM * SDIM,
        out, SDIM, (long)EDIM * SDIM,
        bo, 1.0f / 9.0f);
}

// round 3
// speedup vs baseline: 1.1238x; 1.1238x over previous
#include <cuda_runtime.h>
#include <cstdint>

#define SDIM 2048
#define EDIM 256
#define BDIM 8

__device__ float g_Q[BDIM * SDIM * EDIM];      // Q[b][s][f]
__device__ float g_attn[BDIM * SDIM * 16];     // 9 weights per (b,s), stride 16
__device__ float g_poolT[BDIM * SDIM * EDIM];  // pooled^T [b][s][e]

static __device__ __forceinline__ uint32_t f2tf32(float f) {
    uint32_t u;
    asm("cvt.rn.tf32.f32 %0, %1;" : "=r"(u) : "f"(f));
    return u;
}

// mma.sync m16n8k8 tf32: D += A*B  (row.col), fp32 accum
static __device__ __forceinline__ void mma_tf32(float* d, const uint32_t* a, const uint32_t* b) {
    asm volatile(
        "mma.sync.aligned.m16n8k8.row.col.f32.tf32.tf32.f32 "
        "{%0,%1,%2,%3}, {%4,%5,%6,%7}, {%8,%9}, {%0,%1,%2,%3};"
        : "+f"(d[0]), "+f"(d[1]), "+f"(d[2]), "+f"(d[3])
        : "r"(a[0]), "r"(a[1]), "r"(a[2]), "r"(a[3]), "r"(b[0]), "r"(b[1]));
}

// Fragment-order SMEM offsets (floats) for the m16n8k8 tf32 lane maps.
// A tile: 128(m) x 32(k); fragment a0..a3: row=lane>>2 (+8), k=lane&3 (+4)
static __device__ __forceinline__ int offA(int m, int k) {
    int lane = (m & 7) * 4 + (k & 3);
    int j = ((m >> 3) & 1) | (((k >> 2) & 1) << 1);
    return ((((m >> 5) * 2 + ((m >> 4) & 1)) * 4 + (k >> 3)) * 128) + lane * 4 + j;
}
// B tile: 128(n) x 32(k); fragment b0,b1: n=lane>>2, k=lane&3 (+4)
static __device__ __forceinline__ int offB(int n, int k) {
    int lane = (n & 7) * 4 + (k & 3);
    int slot = (k >> 2) & 1;
    return ((((n >> 6) * 8 + ((n >> 3) & 7)) * 4 + (k >> 3)) * 64) + lane * 2 + slot;
}

// ---------------------------------------------------------------------------
// tf32 tensor-core GEMM: C[m][n] = (sum_k a[m][k]*b[n][k] + bias) * scale
// BM=BN=128, K=256 (8 chunks of BK=32). 256 threads = 8 warps (4m x 2n),
// warp tile 32x64. Double-buffered fragment-order SMEM.
// TRANS_A=1: a[m][k] = A[k*lda + m]  (x tensor; transpose folded into scatter)
// TRANS_A=0: a[m][k] = A[m*lda + k]  (K-major rows)
// b[n][k] = B[n*ldb + k] always. BIAS_M: bias indexed by m, else by n.
// ---------------------------------------------------------------------------
template <int TRANS_A, int BIAS_M>
__global__ void __launch_bounds__(256, 1)
gemm_mma(const float* __restrict__ A, int lda, long sA,
         const float* __restrict__ B, int ldb, long sB,
         float* __restrict__ C, int ldc, long sC,
         const float* __restrict__ bias, float scale) {
    extern __shared__ uint32_t sm[];  // [2][4096] A | [2][4096] B
    uint32_t* As[2] = {sm, sm + 4096};
    uint32_t* Bs[2] = {sm + 8192, sm + 12288};

    const int tid = threadIdx.x, lane = tid & 31, wid = tid >> 5;
    const int wm = wid & 3, wn = wid >> 2;
    const int bn0 = blockIdx.x * 128, bm0 = blockIdx.y * 128;
    A += sA * blockIdx.z; B += sB * blockIdx.z; C += sC * blockIdx.z;

    float d[2][8][4];
#pragma unroll
    for (int mt = 0; mt < 2; mt++)
#pragma unroll
        for (int nt = 0; nt < 8; nt++)
#pragma unroll
            for (int q = 0; q < 4; q++) d[mt][nt][q] = 0.0f;

    // ---- tile loaders: GMEM float4 -> tf32 -> fragment-order scatter ----
    auto load_A = [&](uint32_t* dst, int k0) {
#pragma unroll
        for (int p = 0; p < 4; p++) {
            int idx = tid + p * 256;
            if (TRANS_A) {
                int kk = idx >> 5, mv = (idx & 31) << 2;  // float4 along m
                float4 v = *(const float4*)(A + (long)(k0 + kk) * lda + bm0 + mv);
                dst[offA(mv + 0, kk)] = f2tf32(v.x);
                dst[offA(mv + 1, kk)] = f2tf32(v.y);
                dst[offA(mv + 2, kk)] = f2tf32(v.z);
                dst[offA(mv + 3, kk)] = f2tf32(v.w);
            } else {
                int r = idx >> 3, kv = (idx & 7) << 2;    // float4 along k
                float4 v = *(const float4*)(A + (long)(bm0 + r) * lda + k0 + kv);
                dst[offA(r, kv + 0)] = f2tf32(v.x);
                dst[offA(r, kv + 1)] = f2tf32(v.y);
                dst[offA(r, kv + 2)] = f2tf32(v.z);
                dst[offA(r, kv + 3)] = f2tf32(v.w);
            }
        }
    };
    auto load_B = [&](uint32_t* dst, int k0) {
#pragma unroll
        for (int p = 0; p < 4; p++) {
            int idx = tid + p * 256;
            int r = idx >> 3, kv = (idx & 7) << 2;
            float4 v = *(const float4*)(B + (long)(bn0 + r) * ldb + k0 + kv);
            dst[offB(r, kv + 0)] = f2tf32(v.x);
            dst[offB(r, kv + 1)] = f2tf32(v.y);
            dst[offB(r, kv + 2)] = f2tf32(v.z);
            dst[offB(r, kv + 3)] = f2tf32(v.w);
        }
    };

    auto compute = [&](int buf) {
#pragma unroll
        for (int k8 = 0; k8 < 4; k8++) {
            uint32_t afr[2][4];
            uint32_t bfr[8][2];
#pragma unroll
            for (int mt = 0; mt < 2; mt++)
                *(uint4*)afr[mt] = *(const uint4*)&As[buf][((wm * 2 + mt) * 4 + k8) * 128 + lane * 4];
#pragma unroll
            for (int nt = 0; nt < 8; nt++)
                *(uint2*)bfr[nt] = *(const uint2*)&Bs[buf][((wn * 8 + nt) * 4 + k8) * 64 + lane * 2];
#pragma unroll
            for (int mt = 0; mt < 2; mt++)
#pragma unroll
                for (int nt = 0; nt < 8; nt++) mma_tf32(d[mt][nt], afr[mt], bfr[nt]);
        }
    };

    // prologue
    load_A(As[0], 0);
    load_B(Bs[0], 0);
    __syncthreads();

#pragma unroll 1
    for (int kt = 0; kt < 8; kt++) {
        int cur = kt & 1;
        if (kt + 1 < 8) {
            load_A(As[cur ^ 1], (kt + 1) * 32);
            load_B(Bs[cur ^ 1], (kt + 1) * 32);
        }
        compute(cur);
        __syncthreads();
    }

    // epilogue: warp tile 32x64, fragment C map: rows lane>>2 (+8), cols 2*(lane&3)
    const int mrow = bm0 + wm * 32 + (lane >> 2);
    const int ncol = bn0 + wn * 64 + (lane & 3) * 2;
#pragma unroll
    for (int mt = 0; mt < 2; mt++) {
        int m0 = mrow + mt * 16;
#pragma unroll
        for (int nt = 0; nt < 8; nt++) {
            int c = ncol + nt * 8;
            float b0, b1, b2;
            if (BIAS_M) { b0 = bias[m0]; b2 = bias[m0 + 8]; b1 = 0.0f; }
            else { b0 = bias[c]; b1 = bias[c + 1]; b2 = 0.0f; }
            float2 lo, hi;
            if (BIAS_M) {
                lo.x = (d[mt][nt][0] + b0) * scale; lo.y = (d[mt][nt][1] + b0) * scale;
                hi.x = (d[mt][nt][2] + b2) * scale; hi.y = (d[mt][nt][3] + b2) * scale;
            } else {
                lo.x = (d[mt][nt][0] + b0) * scale; lo.y = (d[mt][nt][1] + b1) * scale;
                hi.x = (d[mt][nt][2] + b0) * scale; hi.y = (d[mt][nt][3] + b1) * scale;
            }
            *(float2*)(C + (long)m0 * ldc + c) = lo;
            *(float2*)(C + (long)(m0 + 8) * ldc + c) = hi;
        }
    }
}

// ---------------------------------------------------------------------------
// Attention weights: softmax over 9-tap Q-dot window
// ---------------------------------------------------------------------------
__global__ void __launch_bounds__(256) attn_kernel(const float* __restrict__ bq) {
    int b = blockIdx.y;
    int s0 = blockIdx.x * 32;
    __shared__ float Qs[40 * EDIM];

    const float* Qb = g_Q + (long)b * SDIM * EDIM;
    for (int idx = threadIdx.x; idx < 40 * 64; idx += 256) {
        int c = idx >> 6, v = idx & 63;
        int s = s0 - 4 + c;
        float4 val;
        if (s < 0 || s >= SDIM)
            val = ((const float4*)bq)[v];
        else
            val = ((const float4*)(Qb + (long)s * EDIM))[v];
        ((float4*)Qs)[c * 64 + v] = val;
    }
    __syncthreads();

    int w = threadIdx.x >> 5, lane = threadIdx.x & 31;
    const float inv_scale = 1.0f / 24.0f;
#pragma unroll
    for (int i = 0; i < 4; i++) {
        int ls = w * 4 + i;
        int cc = ls + 4;
        float4 c0 = ((float4*)Qs)[cc * 64 + lane];
        float4 c1 = ((float4*)Qs)[cc * 64 + 32 + lane];
        float myd = -1e30f;
#pragma unroll
        for (int l = 0; l < 9; l++) {
            int cl = cc + l - 4;
            float4 q0 = ((float4*)Qs)[cl * 64 + lane];
            float4 q1 = ((float4*)Qs)[cl * 64 + 32 + lane];
            float p = c0.x * q0.x + c0.y * q0.y + c0.z * q0.z + c0.w * q0.w +
                      c1.x * q1.x + c1.y * q1.y + c1.z * q1.z + c1.w * q1.w;
#pragma unroll
            for (int off = 16; off; off >>= 1) p += __shfl_xor_sync(0xffffffffu, p, off);
            if (lane == l) myd = p;
        }
        float eng = myd * inv_scale;
        float m = eng;
#pragma unroll
        for (int off = 16; off; off >>= 1) m = fmaxf(m, __shfl_xor_sync(0xffffffffu, m, off));
        float ev = (lane < 9) ? __expf(eng - m) : 0.0f;
        float sum = ev;
#pragma unroll
        for (int off = 16; off; off >>= 1) sum += __shfl_xor_sync(0xffffffffu, sum, off);
        float a = ev / sum;
        if (lane < 9) g_attn[(long)(b * SDIM + s0 + ls) * 16 + lane] = a;
    }
}

// ---------------------------------------------------------------------------
// Weighted pooling -> TRANSPOSED output pooled^T[b][s][e] (K-major for GEMM2)
// ---------------------------------------------------------------------------
__global__ void __launch_bounds__(256) pool_kernel(const float* __restrict__ x) {
    int b = blockIdx.z;
    int e0 = blockIdx.y * 32;
    int s0 = blockIdx.x * 128;
    __shared__ float a_sm[128 * 9];
    __shared__ float x_sm[32 * 136];

    for (int idx = threadIdx.x; idx < 128 * 9; idx += 256) {
        int i = idx / 9, l = idx - i * 9;
        a_sm[idx] = g_attn[(long)(b * SDIM + s0 + i) * 16 + l];
    }
    const float* xb = x + ((long)b * EDIM + e0) * SDIM;
    for (int idx = threadIdx.x; idx < 32 * 136; idx += 256) {
        int e = idx / 136, j = idx - e * 136;
        int s = s0 - 4 + j;
        x_sm[idx] = (s >= 0 && s < SDIM) ? xb[(long)e * SDIM + s] : 0.0f;
    }
    __syncthreads();

    int ts = threadIdx.x & 31, te = threadIdx.x >> 5;
    float* pt = g_poolT + (long)b * SDIM * EDIM + e0 + te * 4;
#pragma unroll
    for (int si = 0; si < 4; si++) {
        int ls = ts + si * 32;
        float a[9];
#pragma unroll
        for (int l = 0; l < 9; l++) a[l] = a_sm[ls * 9 + l];
        float acc[4];
#pragma unroll
        for (int j = 0; j < 4; j++) {
            int e = te * 4 + j;
            float s = 0.0f;
#pragma unroll
            for (int l = 0; l < 9; l++) s += a[l] * x_sm[e * 136 + ls + l];
            acc[j] = s;
        }
        *(float4*)&pt[(long)(s0 + ls) * EDIM] = make_float4(acc[0], acc[1], acc[2], acc[3]);
    }
}

// ---------------------------------------------------------------------------
extern "C" void kernel_launch(void* const* d_in, const int* in_sizes, int n_in,
                              void* d_out, int out_size) {
    const float* x  = (const float*)d_in[0];
    const float* Wq = (const float*)d_in[1];
    const float* bq = (const float*)d_in[2];
    const float* Wo = (const float*)d_in[3];
    const float* bo = (const float*)d_in[4];
    float* out = (float*)d_out;

    float *Qp, *pt;
    cudaGetSymbolAddress((void**)&Qp, g_Q);
    cudaGetSymbolAddress((void**)&pt, g_poolT);

    const int SMEM = 16384 * 4;  // 64KB: double-buffered A+B fragment tiles
    cudaFuncSetAttribute((const void*)gemm_mma<1, 0>, cudaFuncAttributeMaxDynamicSharedMemorySize, SMEM);
    cudaFuncSetAttribute((const void*)gemm_mma<0, 1>, cudaFuncAttributeMaxDynamicSharedMemorySize, SMEM);

    // 1) Q[b][s][f] = sum_e x[b][e][s]*Wq[f][e] + bq[f]   (m=s, n=f, k=e)
    gemm_mma<1, 0><<<dim3(2, 16, BDIM), 256, SMEM>>>(
        x, SDIM, (long)EDIM * SDIM,
        Wq, EDIM, 0L,
        Qp, EDIM, (long)SDIM * EDIM,
        bq, 1.0f);

    // 2) attention weights
    attn_kernel<<<dim3(SDIM / 32, BDIM), 256>>>(bq);

    // 3) weighted pooling -> pooled^T[s][e]
    pool_kernel<<<dim3(SDIM / 128, EDIM / 32, BDIM), 256>>>(x);

    // 4) out[b][f][s] = (sum_e Wo[f][e]*pooled^T[s][e] + bo[f]) / 9   (m=f, n=s, k=e)
    gemm_mma<0, 1><<<dim3(16, 2, BDIM), 256, SMEM>>>(
        Wo, EDIM, 0L,
        pt, EDIM, (long)SDIM * EDIM,
        out, SDIM, (long)EDIM * SDIM,
        bo, 1.0f / 9.0f);
}

// round 4
// speedup vs baseline: 1.3282x; 1.1818x over previous
#include <cuda_runtime.h>
#include <cstdint>

#define SDIM 2048
#define EDIM 256
#define BDIM 8

__device__ float g_Q[BDIM * SDIM * EDIM];      // Q[b][s][f]
__device__ float g_attn[BDIM * SDIM * 16];     // 9 weights per (b,s), stride 16
__device__ float g_poolT[BDIM * SDIM * EDIM];  // pooled^T [b][s][e]

static __device__ __forceinline__ uint32_t f2tf32(float f) {
    uint32_t u;
    asm("cvt.rn.tf32.f32 %0, %1;" : "=r"(u) : "f"(f));
    return u;
}

// mma.sync m16n8k8 tf32: D += A*B  (row.col), fp32 accum
static __device__ __forceinline__ void mma_tf32(float* d, const uint32_t* a, const uint32_t* b) {
    asm volatile(
        "mma.sync.aligned.m16n8k8.row.col.f32.tf32.tf32.f32 "
        "{%0,%1,%2,%3}, {%4,%5,%6,%7}, {%8,%9}, {%0,%1,%2,%3};"
        : "+f"(d[0]), "+f"(d[1]), "+f"(d[2]), "+f"(d[3])
        : "r"(a[0]), "r"(a[1]), "r"(a[2]), "r"(a[3]), "r"(b[0]), "r"(b[1]));
}

// Fragment-order SMEM offsets (floats) for the m16n8k8 tf32 lane maps.
// A tile: 128(m) x 32(k); fragment a0..a3: row=lane>>2 (+8), k=lane&3 (+4)
static __device__ __forceinline__ int offA(int m, int k) {
    int lane = (m & 7) * 4 + (k & 3);
    int j = ((m >> 3) & 1) | (((k >> 2) & 1) << 1);
    return ((((m >> 5) * 2 + ((m >> 4) & 1)) * 4 + (k >> 3)) * 128) + lane * 4 + j;
}
// B tile: 128(n) x 32(k); fragment b0,b1: n=lane>>2, k=lane&3 (+4)
static __device__ __forceinline__ int offB(int n, int k) {
    int lane = (n & 7) * 4 + (k & 3);
    int slot = (k >> 2) & 1;
    return ((((n >> 6) * 8 + ((n >> 3) & 7)) * 4 + (k >> 3)) * 64) + lane * 2 + slot;
}

// ---------------------------------------------------------------------------
// tf32 tensor-core GEMM: C[m][n] = (sum_k a[m][k]*b[n][k] + bias) * scale
// BM=BN=128, K=256 (8 chunks of BK=32). 256 threads = 8 warps (4m x 2n),
// warp tile 32x64. Double-buffered fragment-order SMEM.
// Mainloop: LDG(kt+1) -> compute(kt) -> STS(kt+1) -> bar  (LDG hidden by MMA).
// TRANS_A=1: a[m][k] = A[k*lda + m]  (x tensor; transpose folded into scatter)
// TRANS_A=0: a[m][k] = A[m*lda + k]  (K-major rows)
// b[n][k] = B[n*ldb + k] always. BIAS_M: bias indexed by m, else by n.
// ---------------------------------------------------------------------------
template <int TRANS_A, int BIAS_M>
__global__ void __launch_bounds__(256, 2)
gemm_mma(const float* __restrict__ A, int lda, long sA,
         const float* __restrict__ B, int ldb, long sB,
         float* __restrict__ C, int ldc, long sC,
         const float* __restrict__ bias, float scale) {
    extern __shared__ uint32_t sm[];  // [2][4096] A | [2][4096] B
    uint32_t* As[2] = {sm, sm + 4096};
    uint32_t* Bs[2] = {sm + 8192, sm + 12288};

    const int tid = threadIdx.x, lane = tid & 31, wid = tid >> 5;
    const int wm = wid & 3, wn = wid >> 2;
    const int bn0 = blockIdx.x * 128, bm0 = blockIdx.y * 128;
    A += sA * blockIdx.z; B += sB * blockIdx.z; C += sC * blockIdx.z;

    float d[2][8][4];
#pragma unroll
    for (int mt = 0; mt < 2; mt++)
#pragma unroll
        for (int nt = 0; nt < 8; nt++)
#pragma unroll
            for (int q = 0; q < 4; q++) d[mt][nt][q] = 0.0f;

    float4 stA[4], stB[4];  // GMEM staging registers

    auto ldg_tile = [&](int k0) {
#pragma unroll
        for (int p = 0; p < 4; p++) {
            int idx = tid + p * 256;
            if (TRANS_A) {
                int kk = idx >> 5, mv = (idx & 31) << 2;  // float4 along m
                stA[p] = *(const float4*)(A + (long)(k0 + kk) * lda + bm0 + mv);
            } else {
                int r = idx >> 3, kv = (idx & 7) << 2;    // float4 along k
                stA[p] = *(const float4*)(A + (long)(bm0 + r) * lda + k0 + kv);
            }
        }
#pragma unroll
        for (int p = 0; p < 4; p++) {
            int idx = tid + p * 256;
            int r = idx >> 3, kv = (idx & 7) << 2;
            stB[p] = *(const float4*)(B + (long)(bn0 + r) * ldb + k0 + kv);
        }
    };

    auto sts_tile = [&](int buf) {
        uint32_t* da = As[buf];
        uint32_t* db = Bs[buf];
#pragma unroll
        for (int p = 0; p < 4; p++) {
            int idx = tid + p * 256;
            if (TRANS_A) {
                int kk = idx >> 5, mv = (idx & 31) << 2;
                da[offA(mv + 0, kk)] = f2tf32(stA[p].x);
                da[offA(mv + 1, kk)] = f2tf32(stA[p].y);
                da[offA(mv + 2, kk)] = f2tf32(stA[p].z);
                da[offA(mv + 3, kk)] = f2tf32(stA[p].w);
            } else {
                int r = idx >> 3, kv = (idx & 7) << 2;
                da[offA(r, kv + 0)] = f2tf32(stA[p].x);
                da[offA(r, kv + 1)] = f2tf32(stA[p].y);
                da[offA(r, kv + 2)] = f2tf32(stA[p].z);
                da[offA(r, kv + 3)] = f2tf32(stA[p].w);
            }
        }
#pragma unroll
        for (int p = 0; p < 4; p++) {
            int idx = tid + p * 256;
            int r = idx >> 3, kv = (idx & 7) << 2;
            db[offB(r, kv + 0)] = f2tf32(stB[p].x);
            db[offB(r, kv + 1)] = f2tf32(stB[p].y);
            db[offB(r, kv + 2)] = f2tf32(stB[p].z);
            db[offB(r, kv + 3)] = f2tf32(stB[p].w);
        }
    };

    auto compute = [&](int buf) {
#pragma unroll
        for (int k8 = 0; k8 < 4; k8++) {
            uint32_t afr[2][4];
            uint32_t bfr[8][2];
#pragma unroll
            for (int mt = 0; mt < 2; mt++)
                *(uint4*)afr[mt] = *(const uint4*)&As[buf][((wm * 2 + mt) * 4 + k8) * 128 + lane * 4];
#pragma unroll
            for (int nt = 0; nt < 8; nt++)
                *(uint2*)bfr[nt] = *(const uint2*)&Bs[buf][((wn * 8 + nt) * 4 + k8) * 64 + lane * 2];
#pragma unroll
            for (int mt = 0; mt < 2; mt++)
#pragma unroll
                for (int nt = 0; nt < 8; nt++) mma_tf32(d[mt][nt], afr[mt], bfr[nt]);
        }
    };

    // prologue: chunk 0
    ldg_tile(0);
    sts_tile(0);
    __syncthreads();

#pragma unroll 1
    for (int kt = 0; kt < 8; kt++) {
        int cur = kt & 1;
        if (kt + 1 < 8) ldg_tile((kt + 1) * 32);  // LDGs in flight during compute
        compute(cur);
        if (kt + 1 < 8) sts_tile(cur ^ 1);        // buffer cur^1 fully drained pre-bar
        __syncthreads();
    }

    // epilogue: warp tile 32x64, fragment C map: rows lane>>2 (+8), cols 2*(lane&3)
    const int mrow = bm0 + wm * 32 + (lane >> 2);
    const int ncol = bn0 + wn * 64 + (lane & 3) * 2;
#pragma unroll
    for (int mt = 0; mt < 2; mt++) {
        int m0 = mrow + mt * 16;
#pragma unroll
        for (int nt = 0; nt < 8; nt++) {
            int c = ncol + nt * 8;
            float b0, b1, b2;
            if (BIAS_M) { b0 = bias[m0]; b2 = bias[m0 + 8]; b1 = 0.0f; }
            else { b0 = bias[c]; b1 = bias[c + 1]; b2 = 0.0f; }
            float2 lo, hi;
            if (BIAS_M) {
                lo.x = (d[mt][nt][0] + b0) * scale; lo.y = (d[mt][nt][1] + b0) * scale;
                hi.x = (d[mt][nt][2] + b2) * scale; hi.y = (d[mt][nt][3] + b2) * scale;
            } else {
                lo.x = (d[mt][nt][0] + b0) * scale; lo.y = (d[mt][nt][1] + b1) * scale;
                hi.x = (d[mt][nt][2] + b0) * scale; hi.y = (d[mt][nt][3] + b1) * scale;
            }
            *(float2*)(C + (long)m0 * ldc + c) = lo;
            *(float2*)(C + (long)(m0 + 8) * ldc + c) = hi;
        }
    }
}

// ---------------------------------------------------------------------------
// Attention weights: softmax over 9-tap Q-dot window
// ---------------------------------------------------------------------------
__global__ void __launch_bounds__(256) attn_kernel(const float* __restrict__ bq) {
    int b = blockIdx.y;
    int s0 = blockIdx.x * 32;
    __shared__ float Qs[40 * EDIM];

    const float* Qb = g_Q + (long)b * SDIM * EDIM;
    for (int idx = threadIdx.x; idx < 40 * 64; idx += 256) {
        int c = idx >> 6, v = idx & 63;
        int s = s0 - 4 + c;
        float4 val;
        if (s < 0 || s >= SDIM)
            val = ((const float4*)bq)[v];
        else
            val = ((const float4*)(Qb + (long)s * EDIM))[v];
        ((float4*)Qs)[c * 64 + v] = val;
    }
    __syncthreads();

    int w = threadIdx.x >> 5, lane = threadIdx.x & 31;
    const float inv_scale = 1.0f / 24.0f;
#pragma unroll
    for (int i = 0; i < 4; i++) {
        int ls = w * 4 + i;
        int cc = ls + 4;
        float4 c0 = ((float4*)Qs)[cc * 64 + lane];
        float4 c1 = ((float4*)Qs)[cc * 64 + 32 + lane];
        float myd = -1e30f;
#pragma unroll
        for (int l = 0; l < 9; l++) {
            int cl = cc + l - 4;
            float4 q0 = ((float4*)Qs)[cl * 64 + lane];
            float4 q1 = ((float4*)Qs)[cl * 64 + 32 + lane];
            float p = c0.x * q0.x + c0.y * q0.y + c0.z * q0.z + c0.w * q0.w +
                      c1.x * q1.x + c1.y * q1.y + c1.z * q1.z + c1.w * q1.w;
#pragma unroll
            for (int off = 16; off; off >>= 1) p += __shfl_xor_sync(0xffffffffu, p, off);
            if (lane == l) myd = p;
        }
        float eng = myd * inv_scale;
        float m = eng;
#pragma unroll
        for (int off = 16; off; off >>= 1) m = fmaxf(m, __shfl_xor_sync(0xffffffffu, m, off));
        float ev = (lane < 9) ? __expf(eng - m) : 0.0f;
        float sum = ev;
#pragma unroll
        for (int off = 16; off; off >>= 1) sum += __shfl_xor_sync(0xffffffffu, sum, off);
        float a = ev / sum;
        if (lane < 9) g_attn[(long)(b * SDIM + s0 + ls) * 16 + lane] = a;
    }
}

// ---------------------------------------------------------------------------
// Weighted pooling -> TRANSPOSED output pooled^T[b][s][e] (K-major for GEMM2)
// ---------------------------------------------------------------------------
__global__ void __launch_bounds__(256) pool_kernel(const float* __restrict__ x) {
    int b = blockIdx.z;
    int e0 = blockIdx.y * 32;
    int s0 = blockIdx.x * 128;
    __shared__ float a_sm[128 * 9];
    __shared__ float x_sm[32 * 136];

    for (int idx = threadIdx.x; idx < 128 * 9; idx += 256) {
        int i = idx / 9, l = idx - i * 9;
        a_sm[idx] = g_attn[(long)(b * SDIM + s0 + i) * 16 + l];
    }
    const float* xb = x + ((long)b * EDIM + e0) * SDIM;
    for (int idx = threadIdx.x; idx < 32 * 136; idx += 256) {
        int e = idx / 136, j = idx - e * 136;
        int s = s0 - 4 + j;
        x_sm[idx] = (s >= 0 && s < SDIM) ? xb[(long)e * SDIM + s] : 0.0f;
    }
    __syncthreads();

    int ts = threadIdx.x & 31, te = threadIdx.x >> 5;
    float* pt = g_poolT + (long)b * SDIM * EDIM + e0 + te * 4;
#pragma unroll
    for (int si = 0; si < 4; si++) {
        int ls = ts + si * 32;
        float a[9];
#pragma unroll
        for (int l = 0; l < 9; l++) a[l] = a_sm[ls * 9 + l];
        float acc[4];
#pragma unroll
        for (int j = 0; j < 4; j++) {
            int e = te * 4 + j;
            float s = 0.0f;
#pragma unroll
            for (int l = 0; l < 9; l++) s += a[l] * x_sm[e * 136 + ls + l];
            acc[j] = s;
        }
        *(float4*)&pt[(long)(s0 + ls) * EDIM] = make_float4(acc[0], acc[1], acc[2], acc[3]);
    }
}

// ---------------------------------------------------------------------------
extern "C" void kernel_launch(void* const* d_in, const int* in_sizes, int n_in,
                              void* d_out, int out_size) {
    const float* x  = (const float*)d_in[0];
    const float* Wq = (const float*)d_in[1];
    const float* bq = (const float*)d_in[2];
    const float* Wo = (const float*)d_in[3];
    const float* bo = (const float*)d_in[4];
    float* out = (float*)d_out;

    float *Qp, *pt;
    cudaGetSymbolAddress((void**)&Qp, g_Q);
    cudaGetSymbolAddress((void**)&pt, g_poolT);

    const int SMEM = 16384 * 4;  // 64KB: double-buffered A+B fragment tiles
    cudaFuncSetAttribute((const void*)gemm_mma<1, 0>, cudaFuncAttributeMaxDynamicSharedMemorySize, SMEM);
    cudaFuncSetAttribute((const void*)gemm_mma<0, 1>, cudaFuncAttributeMaxDynamicSharedMemorySize, SMEM);

    // 1) Q[b][s][f] = sum_e x[b][e][s]*Wq[f][e] + bq[f]   (m=s, n=f, k=e)
    gemm_mma<1, 0><<<dim3(2, 16, BDIM), 256, SMEM>>>(
        x, SDIM, (long)EDIM * SDIM,
        Wq, EDIM, 0L,
        Qp, EDIM, (long)SDIM * EDIM,
        bq, 1.0f);

    // 2) attention weights
    attn_kernel<<<dim3(SDIM / 32, BDIM), 256>>>(bq);

    // 3) weighted pooling -> pooled^T[s][e]
    pool_kernel<<<dim3(SDIM / 128, EDIM / 32, BDIM), 256>>>(x);

    // 4) out[b][f][s] = (sum_e Wo[f][e]*pooled^T[s][e] + bo[f]) / 9   (m=f, n=s, k=e)
    gemm_mma<0, 1><<<dim3(16, 2, BDIM), 256, SMEM>>>(
        Wo, EDIM, 0L,
        pt, EDIM, (long)SDIM * EDIM,
        out, SDIM, (long)EDIM * SDIM,
        bo, 1.0f / 9.0f);
}

// round 6
// speedup vs baseline: 1.5969x; 1.2023x over previous
#include <cuda_runtime.h>
#include <cstdint>

#define SDIM 2048
#define EDIM 256
#define BDIM 8

__device__ float g_Q[BDIM * SDIM * EDIM];      // Q[b][s][f]
__device__ float g_attn[BDIM * SDIM * 16];     // 9 weights per (b,s), stride 16
__device__ float g_poolT[BDIM * SDIM * EDIM];  // pooled^T [b][s][e]

static __device__ __forceinline__ uint32_t smem_u32(const void* p) {
    uint32_t a;
    asm("{ .reg .u64 t; cvta.to.shared.u64 t, %1; cvt.u32.u64 %0, t; }" : "=r"(a) : "l"(p));
    return a;
}
static __device__ __forceinline__ void cp4(uint32_t dst, const float* src) {
    asm volatile("cp.async.ca.shared.global [%0], [%1], 4;" :: "r"(dst), "l"(src));
}
static __device__ __forceinline__ void cp16(uint32_t dst, const float* src) {
    asm volatile("cp.async.ca.shared.global [%0], [%1], 16;" :: "r"(dst), "l"(src));
}
static __device__ __forceinline__ void cp_commit() {
    asm volatile("cp.async.commit_group;" ::: "memory");
}
template <int N>
static __device__ __forceinline__ void cp_wait() {
    asm volatile("cp.async.wait_group %0;" :: "n"(N) : "memory");
}
// round-to-nearest fp32 -> tf32 (restores R3/R4 accuracy; HW MMA input is RZ)
static __device__ __forceinline__ uint32_t rntf32(float f) {
    uint32_t u;
    asm("cvt.rn.tf32.f32 %0, %1;" : "=r"(u) : "f"(f));
    return u;
}

// mma.sync m16n8k8 tf32: D += A*B  (row.col), fp32 accum
static __device__ __forceinline__ void mma_tf32(float* d, const uint32_t* a, const uint32_t* b) {
    asm volatile(
        "mma.sync.aligned.m16n8k8.row.col.f32.tf32.tf32.f32 "
        "{%0,%1,%2,%3}, {%4,%5,%6,%7}, {%8,%9}, {%0,%1,%2,%3};"
        : "+f"(d[0]), "+f"(d[1]), "+f"(d[2]), "+f"(d[3])
        : "r"(a[0]), "r"(a[1]), "r"(a[2]), "r"(a[3]), "r"(b[0]), "r"(b[1]));
}

// K-major swizzled SMEM (tile 128 rows x 32 floats, row = 8 x 16B chunks):
// float index of (row, k):  row*32 + ((k>>2) ^ (row&7))*4 + (k&3)
static __device__ __forceinline__ int swz(int row, int k) {
    return row * 32 + (((k >> 2) ^ (row & 7)) << 2) + (k & 3);
}

// ---------------------------------------------------------------------------
// tf32 tensor-core GEMM, cp.async 3-stage pipeline, RN rounding in registers.
// C[m][n] = (sum_k a[m][k]*b[n][k] + bias) * scale
// BM=BN=128, K=256 (8 chunks of BK=32). 256 threads = 8 warps (4m x 2n),
// warp tile 32x64.
// TRANS_A=1: a[m][k] = A[k*lda + m]  (4B cp.async scatter folds transpose)
// TRANS_A=0: a[m][k] = A[m*lda + k]  (16B cp.async)
// b[n][k] = B[n*ldb + k] always. BIAS_M: bias indexed by m, else by n.
// ---------------------------------------------------------------------------
template <int TRANS_A, int BIAS_M>
__global__ void __launch_bounds__(256, 2)
gemm_mma(const float* __restrict__ A, int lda, long sA,
         const float* __restrict__ B, int ldb, long sB,
         float* __restrict__ C, int ldc, long sC,
         const float* __restrict__ bias, float scale) {
    extern __shared__ float sm[];  // 3 stages x (A 4096 | B 4096) floats
    const int tid = threadIdx.x, lane = tid & 31, wid = tid >> 5;
    const int wm = wid & 3, wn = wid >> 2;
    const int bn0 = blockIdx.x * 128, bm0 = blockIdx.y * 128;
    A += sA * blockIdx.z; B += sB * blockIdx.z; C += sC * blockIdx.z;

    const uint32_t smb = smem_u32(sm);

    float d[2][8][4];
#pragma unroll
    for (int mt = 0; mt < 2; mt++)
#pragma unroll
        for (int nt = 0; nt < 8; nt++)
#pragma unroll
            for (int q = 0; q < 4; q++) d[mt][nt][q] = 0.0f;

    // stage fill: A tile + B tile for K-chunk k0 into slot
    auto fill = [&](int slot, int k0) {
        uint32_t abase = smb + slot * 32768;           // bytes: 4096 floats
        uint32_t bbase = abase + 16384;
        if (TRANS_A) {
            // per-element 4B: src contiguous along m
#pragma unroll
            for (int j = 0; j < 16; j++) {
                int kk = (tid >> 7) + j * 2;
                int m = tid & 127;
                cp4(abase + swz(m, kk) * 4, A + (long)(k0 + kk) * lda + bm0 + m);
            }
        } else {
#pragma unroll
            for (int j = 0; j < 4; j++) {
                int c = tid + j * 256;
                int row = c >> 3, ch = c & 7;
                cp16(abase + (row * 32 + ((ch ^ (row & 7)) << 2)) * 4,
                     A + (long)(bm0 + row) * lda + k0 + ch * 4);
            }
        }
#pragma unroll
        for (int j = 0; j < 4; j++) {
            int c = tid + j * 256;
            int row = c >> 3, ch = c & 7;
            cp16(bbase + (row * 32 + ((ch ^ (row & 7)) << 2)) * 4,
                 B + (long)(bn0 + row) * ldb + k0 + ch * 4);
        }
    };

    auto compute = [&](int slot) {
        const float* as = sm + slot * 8192;
        const float* bs = as + 4096;
#pragma unroll
        for (int k8 = 0; k8 < 4; k8++) {
            const int k = k8 * 8 + (lane & 3);
            uint32_t afr[2][4], bfr[8][2];
#pragma unroll
            for (int mt = 0; mt < 2; mt++) {
                int m0 = wm * 32 + mt * 16 + (lane >> 2);
                afr[mt][0] = rntf32(as[swz(m0, k)]);
                afr[mt][1] = rntf32(as[swz(m0 + 8, k)]);
                afr[mt][2] = rntf32(as[swz(m0, k + 4)]);
                afr[mt][3] = rntf32(as[swz(m0 + 8, k + 4)]);
            }
#pragma unroll
            for (int nt = 0; nt < 8; nt++) {
                int n0 = wn * 64 + nt * 8 + (lane >> 2);
                bfr[nt][0] = rntf32(bs[swz(n0, k)]);
                bfr[nt][1] = rntf32(bs[swz(n0, k + 4)]);
            }
#pragma unroll
            for (int mt = 0; mt < 2; mt++)
#pragma unroll
                for (int nt = 0; nt < 8; nt++) mma_tf32(d[mt][nt], afr[mt], bfr[nt]);
        }
    };

    // prologue: stages 0, 1 in flight
    fill(0, 0); cp_commit();
    fill(1, 32); cp_commit();

#pragma unroll 1
    for (int kt = 0; kt < 8; kt++) {
        if (kt == 7) cp_wait<0>(); else cp_wait<1>();
        __syncthreads();
        if (kt + 2 < 8) { fill((kt + 2) % 3, (kt + 2) * 32); cp_commit(); }
        compute(kt % 3);
    }

    // epilogue: fragment C map: rows lane>>2 (+8), cols 2*(lane&3)
    const int mrow = bm0 + wm * 32 + (lane >> 2);
    const int ncol = bn0 + wn * 64 + (lane & 3) * 2;
#pragma unroll
    for (int mt = 0; mt < 2; mt++) {
        int m0 = mrow + mt * 16;
#pragma unroll
        for (int nt = 0; nt < 8; nt++) {
            int c = ncol + nt * 8;
            float b0, b1, b2;
            if (BIAS_M) { b0 = bias[m0]; b2 = bias[m0 + 8]; b1 = 0.0f; }
            else { b0 = bias[c]; b1 = bias[c + 1]; b2 = 0.0f; }
            float2 lo, hi;
            if (BIAS_M) {
                lo.x = (d[mt][nt][0] + b0) * scale; lo.y = (d[mt][nt][1] + b0) * scale;
                hi.x = (d[mt][nt][2] + b2) * scale; hi.y = (d[mt][nt][3] + b2) * scale;
            } else {
                lo.x = (d[mt][nt][0] + b0) * scale; lo.y = (d[mt][nt][1] + b1) * scale;
                hi.x = (d[mt][nt][2] + b0) * scale; hi.y = (d[mt][nt][3] + b1) * scale;
            }
            *(float2*)(C + (long)m0 * ldc + c) = lo;
            *(float2*)(C + (long)(m0 + 8) * ldc + c) = hi;
        }
    }
}

// ---------------------------------------------------------------------------
// Attention weights: softmax over 9-tap Q-dot window
// ---------------------------------------------------------------------------
__global__ void __launch_bounds__(256) attn_kernel(const float* __restrict__ bq) {
    int b = blockIdx.y;
    int s0 = blockIdx.x * 32;
    __shared__ float Qs[40 * EDIM];

    const float* Qb = g_Q + (long)b * SDIM * EDIM;
    for (int idx = threadIdx.x; idx < 40 * 64; idx += 256) {
        int c = idx >> 6, v = idx & 63;
        int s = s0 - 4 + c;
        float4 val;
        if (s < 0 || s >= SDIM)
            val = ((const float4*)bq)[v];
        else
            val = ((const float4*)(Qb + (long)s * EDIM))[v];
        ((float4*)Qs)[c * 64 + v] = val;
    }
    __syncthreads();

    int w = threadIdx.x >> 5, lane = threadIdx.x & 31;
    const float inv_scale = 1.0f / 24.0f;
#pragma unroll
    for (int i = 0; i < 4; i++) {
        int ls = w * 4 + i;
        int cc = ls + 4;
        float4 c0 = ((float4*)Qs)[cc * 64 + lane];
        float4 c1 = ((float4*)Qs)[cc * 64 + 32 + lane];
        float myd = -1e30f;
#pragma unroll
        for (int l = 0; l < 9; l++) {
            int cl = cc + l - 4;
            float4 q0 = ((float4*)Qs)[cl * 64 + lane];
            float4 q1 = ((float4*)Qs)[cl * 64 + 32 + lane];
            float p = c0.x * q0.x + c0.y * q0.y + c0.z * q0.z + c0.w * q0.w +
                      c1.x * q1.x + c1.y * q1.y + c1.z * q1.z + c1.w * q1.w;
#pragma unroll
            for (int off = 16; off; off >>= 1) p += __shfl_xor_sync(0xffffffffu, p, off);
            if (lane == l) myd = p;
        }
        float eng = myd * inv_scale;
        float m = eng;
#pragma unroll
        for (int off = 16; off; off >>= 1) m = fmaxf(m, __shfl_xor_sync(0xffffffffu, m, off));
        float ev = (lane < 9) ? __expf(eng - m) : 0.0f;
        float sum = ev;
#pragma unroll
        for (int off = 16; off; off >>= 1) sum += __shfl_xor_sync(0xffffffffu, sum, off);
        float a = ev / sum;
        if (lane < 9) g_attn[(long)(b * SDIM + s0 + ls) * 16 + lane] = a;
    }
}

// ---------------------------------------------------------------------------
// Weighted pooling -> TRANSPOSED output pooled^T[b][s][e] (K-major for GEMM2)
// ---------------------------------------------------------------------------
__global__ void __launch_bounds__(256) pool_kernel(const float* __restrict__ x) {
    int b = blockIdx.z;
    int e0 = blockIdx.y * 32;
    int s0 = blockIdx.x * 128;
    __shared__ float a_sm[128 * 9];
    __shared__ float x_sm[32 * 136];

    for (int idx = threadIdx.x; idx < 128 * 9; idx += 256) {
        int i = idx / 9, l = idx - i * 9;
        a_sm[idx] = g_attn[(long)(b * SDIM + s0 + i) * 16 + l];
    }
    const float* xb = x + ((long)b * EDIM + e0) * SDIM;
    for (int idx = threadIdx.x; idx < 32 * 136; idx += 256) {
        int e = idx / 136, j = idx - e * 136;
        int s = s0 - 4 + j;
        x_sm[idx] = (s >= 0 && s < SDIM) ? xb[(long)e * SDIM + s] : 0.0f;
    }
    __syncthreads();

    int ts = threadIdx.x & 31, te = threadIdx.x >> 5;
    float* pt = g_poolT + (long)b * SDIM * EDIM + e0 + te * 4;
#pragma unroll
    for (int si = 0; si < 4; si++) {
        int ls = ts + si * 32;
        float a[9];
#pragma unroll
        for (int l = 0; l < 9; l++) a[l] = a_sm[ls * 9 + l];
        float acc[4];
#pragma unroll
        for (int j = 0; j < 4; j++) {
            int e = te * 4 + j;
            float s = 0.0f;
#pragma unroll
            for (int l = 0; l < 9; l++) s += a[l] * x_sm[e * 136 + ls + l];
            acc[j] = s;
        }
        *(float4*)&pt[(long)(s0 + ls) * EDIM] = make_float4(acc[0], acc[1], acc[2], acc[3]);
    }
}

// ---------------------------------------------------------------------------
extern "C" void kernel_launch(void* const* d_in, const int* in_sizes, int n_in,
                              void* d_out, int out_size) {
    const float* x  = (const float*)d_in[0];
    const float* Wq = (const float*)d_in[1];
    const float* bq = (const float*)d_in[2];
    const float* Wo = (const float*)d_in[3];
    const float* bo = (const float*)d_in[4];
    float* out = (float*)d_out;

    float *Qp, *pt;
    cudaGetSymbolAddress((void**)&Qp, g_Q);
    cudaGetSymbolAddress((void**)&pt, g_poolT);

    const int SMEM = 3 * 32768;  // 96KB: 3-stage A+B tiles
    cudaFuncSetAttribute((const void*)gemm_mma<1, 0>, cudaFuncAttributeMaxDynamicSharedMemorySize, SMEM);
    cudaFuncSetAttribute((const void*)gemm_mma<0, 1>, cudaFuncAttributeMaxDynamicSharedMemorySize, SMEM);

    // 1) Q[b][s][f] = sum_e x[b][e][s]*Wq[f][e] + bq[f]   (m=s, n=f, k=e)
    gemm_mma<1, 0><<<dim3(2, 16, BDIM), 256, SMEM>>>(
        x, SDIM, (long)EDIM * SDIM,
        Wq, EDIM, 0L,
        Qp, EDIM, (long)SDIM * EDIM,
        bq, 1.0f);

    // 2) attention weights
    attn_kernel<<<dim3(SDIM / 32, BDIM), 256>>>(bq);

    // 3) weighted pooling -> pooled^T[s][e]
    pool_kernel<<<dim3(SDIM / 128, EDIM / 32, BDIM), 256>>>(x);

    // 4) out[b][f][s] = (sum_e Wo[f][e]*pooled^T[s][e] + bo[f]) / 9   (m=f, n=s, k=e)
    gemm_mma<0, 1><<<dim3(16, 2, BDIM), 256, SMEM>>>(
        Wo, EDIM, 0L,
        pt, EDIM, (long)SDIM * EDIM,
        out, SDIM, (long)EDIM * SDIM,
        bo, 1.0f / 9.0f);
}